// round 9
// baseline (speedup 1.0000x reference)
#include <cuda_runtime.h>
#include <cuda_bf16.h>
#include <math.h>
#include <stdint.h>

#define BB 8
#define TT 8192
#define DD 128
#define SS 128
#define CK 64
#define NC (TT/CK)            // 128 chunks per batch
#define ROWS 128              // rows per CTA tile (2 chunks)
#define NB (BB*TT/ROWS)       // 512 CTAs

// ---------------- device scratch (static; no runtime alloc) ----------------
__device__ float g_hloc[BB*TT*SS];
__device__ float g_p[BB*TT*SS];
__device__ float g_C[BB*TT*SS];
__device__ float g_carry[BB*NC*SS];
__device__ float g_x0[BB*TT];

// packed fp32x2 FMA (PTX ISA 8.6, sm_100 family feature — NOT an 'a' feature)
#define FMA2(acc, a, b) \
    asm("fma.rn.f32x2 %0, %1, %2, %0;" : "+l"(acc) : "l"(a), "l"(b))

__device__ __forceinline__ float acc_sum(unsigned long long a) {
    float lo, hi;
    asm("mov.b64 {%0,%1}, %2;" : "=f"(lo), "=f"(hi) : "l"(a));
    return lo + hi;
}

// ---------------------------------------------------------------------------
// Weight tile in smem: 128 rows (s) x 128 cols (k), fp32, 512B rows.
// 16B-chunk swizzle: chunk c of row s lives at c ^ (s & 31).
//  - global->smem store: warp has s const, c = lane -> XOR is a permutation -> conflict-free
//  - GEMM read: lanes read rows s = 4*tx+i (stride 4) at fixed c ->
//    per 8-lane phase s&31 takes 8 distinct values -> 8 distinct chunks -> conflict-free
// ---------------------------------------------------------------------------
__device__ __forceinline__ void load_w_sw(float* wp, const float* __restrict__ Wg, int tid) {
    const float4* wg4 = (const float4*)Wg;
#pragma unroll
    for (int k = 0; k < 16; k++) {
        int f = tid + k * 256;          // 4096 float4 chunks
        int s = f >> 5, c = f & 31;
        *(float4*)((char*)wp + (((s << 5) + (c ^ (s & 31))) << 4)) = wg4[f];
    }
}

// ---------------------------------------------------------------------------
// 128x128x128 GEMM tile with f32x2 K-pairing.
// Thread (tx = tid&15, ty = tid>>4): rows 8*ty..+7, cols {4tx..+3, 64+4tx..+3}.
// acc[j][i] (i<4 -> colA+i, i>=4 -> colB+i-4) holds 2 K-partials, summed at end.
// ---------------------------------------------------------------------------
__device__ __forceinline__ void gemm2(const float* __restrict__ xs,
                                      const float* __restrict__ wp,
                                      int rowb, int colA, int colB,
                                      unsigned long long acc[8][8]) {
#pragma unroll
    for (int j = 0; j < 8; j++)
#pragma unroll
        for (int i = 0; i < 8; i++) acc[j][i] = 0ULL;

    uint32_t baseA[4], baseB[4];
    int sA31[4], sB31[4];
#pragma unroll
    for (int i = 0; i < 4; i++) {
        int sA = colA + i, sB = colB + i;
        baseA[i] = sA << 5;  sA31[i] = sA & 31;
        baseB[i] = sB << 5;  sB31[i] = sB & 31;
    }
    const char* wpb = (const char*)wp;

#pragma unroll 2
    for (int d0 = 0; d0 < 128; d0 += 4) {
        int c = d0 >> 2;
        ulonglong2 wa[4], wb[4];
#pragma unroll
        for (int i = 0; i < 4; i++) {
            wa[i] = *(const ulonglong2*)(wpb + ((baseA[i] + (c ^ sA31[i])) << 4));
            wb[i] = *(const ulonglong2*)(wpb + ((baseB[i] + (c ^ sB31[i])) << 4));
        }
#pragma unroll
        for (int j = 0; j < 8; j++) {
            ulonglong2 xv = *(const ulonglong2*)(xs + (rowb + j) * 128 + d0);
#pragma unroll
            for (int i = 0; i < 4; i++) {
                FMA2(acc[j][i],     xv.x, wa[i].x);
                FMA2(acc[j][i],     xv.y, wa[i].y);
                FMA2(acc[j][i + 4], xv.x, wb[i].x);
                FMA2(acc[j][i + 4], xv.y, wb[i].y);
            }
        }
    }
}

extern __shared__ float sm[];

// ---------------------------------------------------------------------------
// k1: dt/C/B GEMMs + pointwise + local chunk scan
// smem: xs(->uu) 64KB | wp 64KB | dtS 64KB   = 192KB
// ---------------------------------------------------------------------------
#define XS_OFF 0
#define WP_OFF (128*128)
#define DT_OFF (2*128*128)
#define K1_SMEM (3*128*128*4)

__global__ void __launch_bounds__(256, 1)
k1(const float* __restrict__ x, const float* __restrict__ log_A,
   const float* __restrict__ W_B, const float* __restrict__ W_C,
   const float* __restrict__ W_dt, const float* __restrict__ b_dt) {
    float* xs  = sm + XS_OFF;   // also uu after B GEMM
    float* wp  = sm + WP_OFF;
    float* dtS = sm + DT_OFF;

    const int tid = threadIdx.x;
    const int row0 = blockIdx.x * ROWS;
    const int tx = tid & 15, ty = tid >> 4;
    const int colA = 4 * tx, colB = 64 + 4 * tx, rowb = 8 * ty;

    // x tile (row-major, pitch 128) + x0 stash
    {
        const float4* xg = (const float4*)(x + (size_t)row0 * DD);
        float4* xs4 = (float4*)xs;
#pragma unroll
        for (int k = 0; k < 16; k++) xs4[tid + k * 256] = xg[tid + k * 256];
    }
    if (tid < 128) g_x0[row0 + tid] = x[(size_t)(row0 + tid) * DD];

    load_w_sw(wp, W_dt, tid);
    __syncthreads();

    unsigned long long acc[8][8];

    // ---- dt GEMM + softplus -> dtS ----
    gemm2(xs, wp, rowb, colA, colB, acc);
    {
        float bA[4], bBv[4];
#pragma unroll
        for (int i = 0; i < 4; i++) { bA[i] = b_dt[colA + i]; bBv[i] = b_dt[colB + i]; }
#pragma unroll
        for (int j = 0; j < 8; j++) {
            float4 va, vb;
            float* pa = &va.x; float* pb = &vb.x;
#pragma unroll
            for (int i = 0; i < 4; i++) {
                float z = acc_sum(acc[j][i]) + bA[i];
                float sp = fmaxf(z, 0.0f) + log1pf(__expf(-fabsf(z)));
                pa[i] = fminf(sp, 1.0f);
                z = acc_sum(acc[j][i + 4]) + bBv[i];
                sp = fmaxf(z, 0.0f) + log1pf(__expf(-fabsf(z)));
                pb[i] = fminf(sp, 1.0f);
            }
            *(float4*)(dtS + (rowb + j) * 128 + colA) = va;
            *(float4*)(dtS + (rowb + j) * 128 + colB) = vb;
        }
    }
    __syncthreads();

    // ---- C GEMM -> global ----
    load_w_sw(wp, W_C, tid);
    __syncthreads();
    gemm2(xs, wp, rowb, colA, colB, acc);
#pragma unroll
    for (int j = 0; j < 8; j++) {
        float4 va = make_float4(acc_sum(acc[j][0]), acc_sum(acc[j][1]),
                                acc_sum(acc[j][2]), acc_sum(acc[j][3]));
        float4 vb = make_float4(acc_sum(acc[j][4]), acc_sum(acc[j][5]),
                                acc_sum(acc[j][6]), acc_sum(acc[j][7]));
        *(float4*)(g_C + (size_t)(row0 + rowb + j) * SS + colA) = va;
        *(float4*)(g_C + (size_t)(row0 + rowb + j) * SS + colB) = vb;
    }
    __syncthreads();

    // ---- B GEMM -> u = Bx*dt into xs region (xs dead after this GEMM) ----
    load_w_sw(wp, W_B, tid);
    __syncthreads();
    gemm2(xs, wp, rowb, colA, colB, acc);
    __syncthreads();   // everyone done reading xs
#pragma unroll
    for (int j = 0; j < 8; j++) {
        float4 da = *(const float4*)(dtS + (rowb + j) * 128 + colA);
        float4 db = *(const float4*)(dtS + (rowb + j) * 128 + colB);
        float4 va = make_float4(acc_sum(acc[j][0]) * da.x, acc_sum(acc[j][1]) * da.y,
                                acc_sum(acc[j][2]) * da.z, acc_sum(acc[j][3]) * da.w);
        float4 vb = make_float4(acc_sum(acc[j][4]) * db.x, acc_sum(acc[j][5]) * db.y,
                                acc_sum(acc[j][6]) * db.z, acc_sum(acc[j][7]) * db.w);
        *(float4*)(xs + (rowb + j) * 128 + colA) = va;
        *(float4*)(xs + (rowb + j) * 128 + colB) = vb;
    }
    __syncthreads();

    // ---- local scan: 2 chunks x 128 states ----
    {
        const int chunk = tid >> 7, s = tid & 127;
        const float As = -fminf(expf(log_A[s]), 10.0f);
        const float* dts = dtS + chunk * 64 * 128 + s;
        const float* uus = xs  + chunk * 64 * 128 + s;
        size_t gb = (size_t)(row0 + chunk * 64) * SS + s;
        float cum = 0.0f, Ssum = 0.0f;
#pragma unroll 4
        for (int t = 0; t < CK; t++) {
            float dt = dts[t * 128];
            float la = fminf(fmaxf(dt * As, -0.5f), 0.0f);
            cum += la;
            float logp = fmaxf(cum, -30.0f);
            float pv = __expf(logp), pinv = __expf(-logp);
            Ssum = fmaf(uus[t * 128], pinv, Ssum);
            g_hloc[gb + (size_t)t * 128] = pv * Ssum;
            g_p[gb + (size_t)t * 128] = pv;
        }
    }
}

// ---------------------------------------------------------------------------
// k2: cross-chunk carry scan
// ---------------------------------------------------------------------------
__global__ void k2_carry() {
    const int b = blockIdx.x, s = threadIdx.x;
    float h0 = 0.0f;
    for (int c0 = 0; c0 < NC; c0 += 16) {
        float hl[16], pp[16];
#pragma unroll
        for (int k = 0; k < 16; k++) {
            size_t idx = (size_t)(b * TT + (c0 + k) * CK + (CK - 1)) * SS + s;
            hl[k] = g_hloc[idx];
            pp[k] = g_p[idx];
        }
#pragma unroll
        for (int k = 0; k < 16; k++) {
            g_carry[(size_t)(b * NC + c0 + k) * SS + s] = h0;
            h0 = fmaf(pp[k], h0, hl[k]);
        }
    }
}

// ---------------------------------------------------------------------------
// k3: h = hloc + p*h0; y = sum(C*h); out = h@W_out^T + y*x0
// smem: hs 64KB | wp 64KB | ysh 512B | h0s 1KB | x0s 512B
// ---------------------------------------------------------------------------
#define HS_OFF 0
#define WP3_OFF (128*128)
#define YS_OFF (2*128*128)
#define H0_OFF (YS_OFF + 128)
#define X0_OFF (H0_OFF + 256)
#define K3_SMEM ((X0_OFF + 128) * 4)

__global__ void __launch_bounds__(256, 1)
k3(const float* __restrict__ W_out, float* __restrict__ out) {
    float* hs  = sm + HS_OFF;
    float* wp  = sm + WP3_OFF;
    float* ysh = sm + YS_OFF;
    float* h0s = sm + H0_OFF;
    float* x0s = sm + X0_OFF;

    const int tid = threadIdx.x;
    const int row0 = blockIdx.x * ROWS;
    const int b = row0 / TT;
    const int c0 = (row0 % TT) / CK;

    h0s[tid] = g_carry[(size_t)(b * NC + c0 + (tid >> 7)) * SS + (tid & 127)];
    if (tid < 128) x0s[tid] = g_x0[row0 + tid];
    load_w_sw(wp, W_out, tid);
    __syncthreads();

    // h assembly + y reduction: warp wgrp handles rows wgrp*16..+15, lane covers 4 s
    {
        const int l = tid & 31, wgrp = tid >> 5;
        const int s4 = 4 * l;
#pragma unroll 2
        for (int rr = 0; rr < 16; rr++) {
            int r = wgrp * 16 + rr;
            size_t base = (size_t)(row0 + r) * SS + s4;
            float4 hl4 = *(const float4*)(g_hloc + base);
            float4 pp4 = *(const float4*)(g_p + base);
            float4 cc4 = *(const float4*)(g_C + base);
            float4 h04 = *(const float4*)(h0s + (r >> 6) * 128 + s4);
            float4 h;
            h.x = fmaf(pp4.x, h04.x, hl4.x);
            h.y = fmaf(pp4.y, h04.y, hl4.y);
            h.z = fmaf(pp4.z, h04.z, hl4.z);
            h.w = fmaf(pp4.w, h04.w, hl4.w);
            *(float4*)(hs + r * 128 + s4) = h;
            float yp = cc4.x * h.x + cc4.y * h.y + cc4.z * h.z + cc4.w * h.w;
#pragma unroll
            for (int d = 16; d; d >>= 1) yp += __shfl_xor_sync(0xffffffffu, yp, d);
            if (l == 0) ysh[r] = yp;
        }
    }
    __syncthreads();

    // out GEMM
    const int tx = tid & 15, ty = tid >> 4;
    const int colA = 4 * tx, colB = 64 + 4 * tx, rowb = 8 * ty;
    unsigned long long acc[8][8];
    gemm2(hs, wp, rowb, colA, colB, acc);
#pragma unroll
    for (int j = 0; j < 8; j++) {
        float yx = ysh[rowb + j] * x0s[rowb + j];
        float4 va = make_float4(acc_sum(acc[j][0]) + yx, acc_sum(acc[j][1]) + yx,
                                acc_sum(acc[j][2]) + yx, acc_sum(acc[j][3]) + yx);
        float4 vb = make_float4(acc_sum(acc[j][4]) + yx, acc_sum(acc[j][5]) + yx,
                                acc_sum(acc[j][6]) + yx, acc_sum(acc[j][7]) + yx);
        *(float4*)(out + (size_t)(row0 + rowb + j) * DD + colA) = va;
        *(float4*)(out + (size_t)(row0 + rowb + j) * DD + colB) = vb;
    }
}

// ---------------------------------------------------------------------------
// Launch
// ---------------------------------------------------------------------------
extern "C" void kernel_launch(void* const* d_in, const int* in_sizes, int n_in,
                              void* d_out, int out_size) {
    const float* x     = (const float*)d_in[0];
    const float* log_A = (const float*)d_in[1];
    const float* W_B   = (const float*)d_in[2];
    const float* W_C   = (const float*)d_in[3];
    const float* W_dt  = (const float*)d_in[4];
    const float* b_dt  = (const float*)d_in[5];
    const float* W_out = (const float*)d_in[6];
    float* out = (float*)d_out;

    cudaFuncSetAttribute(k1, cudaFuncAttributeMaxDynamicSharedMemorySize, K1_SMEM);
    cudaFuncSetAttribute(k3, cudaFuncAttributeMaxDynamicSharedMemorySize, K3_SMEM);

    k1<<<NB, 256, K1_SMEM>>>(x, log_A, W_B, W_C, W_dt, b_dt);
    k2_carry<<<BB, 128>>>();
    k3<<<NB, 256, K3_SMEM>>>(W_out, out);
}

// round 11
// speedup vs baseline: 1.4761x; 1.4761x over previous
#include <cuda_runtime.h>
#include <cuda_bf16.h>
#include <math.h>
#include <stdint.h>

#define BB 8
#define TT 8192
#define DD 128
#define SS 128
#define CK 64
#define NC (TT/CK)            // 128 chunks per batch
#define ROWS 128              // rows per CTA tile (2 chunks)
#define NB (BB*TT/ROWS)       // 512 CTAs
#define NTHR 512

// ---------------- device scratch (static; no runtime alloc) ----------------
__device__ float g_hloc[BB*TT*SS];
__device__ float g_p[BB*TT*SS];
__device__ float g_C[BB*TT*SS];
__device__ float g_carry[BB*NC*SS];
__device__ float g_x0[BB*TT];

// packed fp32x2 FMA (PTX ISA 8.6, sm_100 family feature)
#define FMA2(acc, a, b) \
    asm("fma.rn.f32x2 %0, %1, %2, %0;" : "+l"(acc) : "l"(a), "l"(b))

__device__ __forceinline__ float acc_sum(unsigned long long a) {
    float lo, hi;
    asm("mov.b64 {%0,%1}, %2;" : "=f"(lo), "=f"(hi) : "l"(a));
    return lo + hi;
}

// ---------------------------------------------------------------------------
// Weight tile: 128 rows (s) x 128 cols (k) fp32, 512B/row.
// 16B chunk c of row s stored at chunk index c ^ ((s>>2)&7).
//   store: warp has fixed s, c = lane -> XOR permutation -> conflict-free
//   gemm read: s = 4*tx+i, fixed c -> chunk = c ^ (tx&7); per 8-lane phase
//              tx&7 distinct -> chunk mod 8 distinct -> distinct bank groups.
// Byte address decomposes as (s<<9) ^ (chunk<<4) -> per-load addr = P ^ (c<<4).
// ---------------------------------------------------------------------------
__device__ __forceinline__ void load_w_sw(float* wp, const float* __restrict__ Wg, int tid) {
    const float4* wg4 = (const float4*)Wg;
#pragma unroll
    for (int k = 0; k < 8; k++) {
        int f = tid + k * NTHR;         // 4096 float4 chunks
        int s = f >> 5, c = f & 31;
        uint32_t addr = ((uint32_t)s << 9) ^ ((uint32_t)(c ^ ((s >> 2) & 7)) << 4);
        *(float4*)((char*)wp + addr) = wg4[f];
    }
}

// ---------------------------------------------------------------------------
// 128x128x128 GEMM tile, 512 threads, f32x2 K-pairing.
// tx = tid&31 -> cols 4tx..4tx+3 ; ty = tid>>5 -> rows 8ty..8ty+7.
// x loads are warp-uniform (broadcast); w loads conflict-free per swizzle.
// ---------------------------------------------------------------------------
__device__ __forceinline__ void gemm512(const float* __restrict__ xs,
                                        const float* __restrict__ wp,
                                        int rowb, int col,
                                        unsigned long long acc[8][4]) {
#pragma unroll
    for (int j = 0; j < 8; j++)
#pragma unroll
        for (int i = 0; i < 4; i++) acc[j][i] = 0ULL;

    uint32_t P[4];
#pragma unroll
    for (int i = 0; i < 4; i++) {
        int s = col + i;
        P[i] = ((uint32_t)s << 9) ^ ((uint32_t)((s >> 2) & 7) << 4);
    }
    const char* wpb = (const char*)wp;

#pragma unroll 4
    for (int c = 0; c < 32; c++) {
        ulonglong2 wv[4];
#pragma unroll
        for (int i = 0; i < 4; i++)
            wv[i] = *(const ulonglong2*)(wpb + (P[i] ^ ((uint32_t)c << 4)));
#pragma unroll
        for (int j = 0; j < 8; j++) {
            ulonglong2 xv = *(const ulonglong2*)(xs + (rowb + j) * 128 + c * 4);
#pragma unroll
            for (int i = 0; i < 4; i++) {
                FMA2(acc[j][i], xv.x, wv[i].x);
                FMA2(acc[j][i], xv.y, wv[i].y);
            }
        }
    }
}

extern __shared__ float sm[];

// ---------------------------------------------------------------------------
// k1: dt/C/B GEMMs + pointwise + local chunk scan
// smem: xs(->uu) 64KB | wp 64KB | dtS 64KB = 192KB
// ---------------------------------------------------------------------------
#define XS_OFF 0
#define WP_OFF (128*128)
#define DT_OFF (2*128*128)
#define K1_SMEM (3*128*128*4)

__global__ void __launch_bounds__(NTHR, 1)
k1(const float* __restrict__ x, const float* __restrict__ log_A,
   const float* __restrict__ W_B, const float* __restrict__ W_C,
   const float* __restrict__ W_dt, const float* __restrict__ b_dt) {
    float* xs  = sm + XS_OFF;   // becomes uu after B GEMM
    float* wp  = sm + WP_OFF;
    float* dtS = sm + DT_OFF;

    const int tid = threadIdx.x;
    const int row0 = blockIdx.x * ROWS;
    const int tx = tid & 31, ty = tid >> 5;
    const int col = 4 * tx, rowb = 8 * ty;

    // x tile (row-major, pitch 128) + x0 stash
    {
        const float4* xg = (const float4*)(x + (size_t)row0 * DD);
        float4* xs4 = (float4*)xs;
#pragma unroll
        for (int k = 0; k < 8; k++) xs4[tid + k * NTHR] = xg[tid + k * NTHR];
    }
    if (tid < 128) g_x0[row0 + tid] = x[(size_t)(row0 + tid) * DD];

    load_w_sw(wp, W_dt, tid);
    __syncthreads();

    unsigned long long acc[8][4];

    // ---- dt GEMM + softplus -> dtS ----
    gemm512(xs, wp, rowb, col, acc);
    {
        float bi[4];
#pragma unroll
        for (int i = 0; i < 4; i++) bi[i] = b_dt[col + i];
#pragma unroll
        for (int j = 0; j < 8; j++) {
            float4 v;
            float* pv = &v.x;
#pragma unroll
            for (int i = 0; i < 4; i++) {
                float z = acc_sum(acc[j][i]) + bi[i];
                float sp = fmaxf(z, 0.0f) + log1pf(__expf(-fabsf(z)));
                pv[i] = fminf(sp, 1.0f);
            }
            *(float4*)(dtS + (rowb + j) * 128 + col) = v;
        }
    }
    __syncthreads();

    // ---- C GEMM -> global ----
    load_w_sw(wp, W_C, tid);
    __syncthreads();
    gemm512(xs, wp, rowb, col, acc);
#pragma unroll
    for (int j = 0; j < 8; j++) {
        float4 v = make_float4(acc_sum(acc[j][0]), acc_sum(acc[j][1]),
                               acc_sum(acc[j][2]), acc_sum(acc[j][3]));
        *(float4*)(g_C + (size_t)(row0 + rowb + j) * SS + col) = v;
    }
    __syncthreads();

    // ---- B GEMM -> u = Bx*dt into xs (xs dead after this GEMM) ----
    load_w_sw(wp, W_B, tid);
    __syncthreads();
    gemm512(xs, wp, rowb, col, acc);
    __syncthreads();   // all reads of xs complete
#pragma unroll
    for (int j = 0; j < 8; j++) {
        float4 d = *(const float4*)(dtS + (rowb + j) * 128 + col);
        float4 v = make_float4(acc_sum(acc[j][0]) * d.x, acc_sum(acc[j][1]) * d.y,
                               acc_sum(acc[j][2]) * d.z, acc_sum(acc[j][3]) * d.w);
        *(float4*)(xs + (rowb + j) * 128 + col) = v;
    }
    __syncthreads();

    // ---- local scan: 2 chunks x 128 states (threads 0..255) ----
    if (tid < 256) {
        const int chunk = tid >> 7, s = tid & 127;
        const float As = -fminf(expf(log_A[s]), 10.0f);
        const float* dts = dtS + chunk * 64 * 128 + s;
        const float* uus = xs  + chunk * 64 * 128 + s;
        size_t gb = (size_t)(row0 + chunk * 64) * SS + s;
        float cum = 0.0f, Ssum = 0.0f;
#pragma unroll 4
        for (int t = 0; t < CK; t++) {
            float dt = dts[t * 128];
            float la = fminf(fmaxf(dt * As, -0.5f), 0.0f);
            cum += la;
            float logp = fmaxf(cum, -30.0f);
            float pv = __expf(logp), pinv = __expf(-logp);
            Ssum = fmaf(uus[t * 128], pinv, Ssum);
            g_hloc[gb + (size_t)t * 128] = pv * Ssum;
            g_p[gb + (size_t)t * 128] = pv;
        }
    }
}

// ---------------------------------------------------------------------------
// k2: cross-chunk carry scan
// ---------------------------------------------------------------------------
__global__ void k2_carry() {
    const int b = blockIdx.x, s = threadIdx.x;
    float h0 = 0.0f;
    for (int c0 = 0; c0 < NC; c0 += 16) {
        float hl[16], pp[16];
#pragma unroll
        for (int k = 0; k < 16; k++) {
            size_t idx = (size_t)(b * TT + (c0 + k) * CK + (CK - 1)) * SS + s;
            hl[k] = g_hloc[idx];
            pp[k] = g_p[idx];
        }
#pragma unroll
        for (int k = 0; k < 16; k++) {
            g_carry[(size_t)(b * NC + c0 + k) * SS + s] = h0;
            h0 = fmaf(pp[k], h0, hl[k]);
        }
    }
}

// ---------------------------------------------------------------------------
// k3: h = hloc + p*h0; y = sum(C*h); out = h@W_out^T + y*x0
// smem: hs 64KB | wp 64KB | ysh/h0s/x0s small
// ---------------------------------------------------------------------------
#define HS_OFF 0
#define WP3_OFF (128*128)
#define YS_OFF (2*128*128)
#define H0_OFF (YS_OFF + 128)
#define X0_OFF (H0_OFF + 256)
#define K3_SMEM ((X0_OFF + 128) * 4)

__global__ void __launch_bounds__(NTHR, 1)
k3(const float* __restrict__ W_out, float* __restrict__ out) {
    float* hs  = sm + HS_OFF;
    float* wp  = sm + WP3_OFF;
    float* ysh = sm + YS_OFF;
    float* h0s = sm + H0_OFF;
    float* x0s = sm + X0_OFF;

    const int tid = threadIdx.x;
    const int row0 = blockIdx.x * ROWS;
    const int b = row0 / TT;
    const int c0 = (row0 % TT) / CK;

    if (tid < 256) h0s[tid] = g_carry[(size_t)(b * NC + c0 + (tid >> 7)) * SS + (tid & 127)];
    if (tid < 128) x0s[tid] = g_x0[row0 + tid];
    load_w_sw(wp, W_out, tid);
    __syncthreads();

    // h assembly + y reduction: 16 warps x 8 rows, lane covers 4 s
    {
        const int l = tid & 31, wgrp = tid >> 5;
        const int s4 = 4 * l;
#pragma unroll 2
        for (int rr = 0; rr < 8; rr++) {
            int r = wgrp * 8 + rr;
            size_t base = (size_t)(row0 + r) * SS + s4;
            float4 hl4 = *(const float4*)(g_hloc + base);
            float4 pp4 = *(const float4*)(g_p + base);
            float4 cc4 = *(const float4*)(g_C + base);
            float4 h04 = *(const float4*)(h0s + (r >> 6) * 128 + s4);
            float4 h;
            h.x = fmaf(pp4.x, h04.x, hl4.x);
            h.y = fmaf(pp4.y, h04.y, hl4.y);
            h.z = fmaf(pp4.z, h04.z, hl4.z);
            h.w = fmaf(pp4.w, h04.w, hl4.w);
            *(float4*)(hs + r * 128 + s4) = h;
            float yp = cc4.x * h.x + cc4.y * h.y + cc4.z * h.z + cc4.w * h.w;
#pragma unroll
            for (int d = 16; d; d >>= 1) yp += __shfl_xor_sync(0xffffffffu, yp, d);
            if (l == 0) ysh[r] = yp;
        }
    }
    __syncthreads();

    // out GEMM
    const int tx = tid & 31, ty = tid >> 5;
    const int col = 4 * tx, rowb = 8 * ty;
    unsigned long long acc[8][4];
    gemm512(hs, wp, rowb, col, acc);
#pragma unroll
    for (int j = 0; j < 8; j++) {
        float yx = ysh[rowb + j] * x0s[rowb + j];
        float4 v = make_float4(acc_sum(acc[j][0]) + yx, acc_sum(acc[j][1]) + yx,
                               acc_sum(acc[j][2]) + yx, acc_sum(acc[j][3]) + yx);
        *(float4*)(out + (size_t)(row0 + rowb + j) * DD + col) = v;
    }
}

// ---------------------------------------------------------------------------
// Launch
// ---------------------------------------------------------------------------
extern "C" void kernel_launch(void* const* d_in, const int* in_sizes, int n_in,
                              void* d_out, int out_size) {
    const float* x     = (const float*)d_in[0];
    const float* log_A = (const float*)d_in[1];
    const float* W_B   = (const float*)d_in[2];
    const float* W_C   = (const float*)d_in[3];
    const float* W_dt  = (const float*)d_in[4];
    const float* b_dt  = (const float*)d_in[5];
    const float* W_out = (const float*)d_in[6];
    float* out = (float*)d_out;

    cudaFuncSetAttribute(k1, cudaFuncAttributeMaxDynamicSharedMemorySize, K1_SMEM);
    cudaFuncSetAttribute(k3, cudaFuncAttributeMaxDynamicSharedMemorySize, K3_SMEM);

    k1<<<NB, NTHR, K1_SMEM>>>(x, log_A, W_B, W_C, W_dt, b_dt);
    k2_carry<<<BB, 128>>>();
    k3<<<NB, NTHR, K3_SMEM>>>(W_out, out);
}

// round 13
// speedup vs baseline: 1.6851x; 1.1416x over previous
#include <cuda_runtime.h>
#include <cuda_bf16.h>
#include <math.h>
#include <stdint.h>

#define BB 8
#define TT 8192
#define DD 128
#define SS 128
#define CK 64
#define NC (TT/CK)            // 128 chunks per batch
#define ROWS 64               // rows per CTA tile (1 chunk)
#define NB (BB*TT/ROWS)       // 1024 CTAs
#define NTHR 256

// ---------------- device scratch (static; no runtime alloc) ----------------
__device__ float g_hloc[BB*TT*SS];
__device__ float g_p[BB*TT*SS];
__device__ float g_C[BB*TT*SS];
__device__ float g_carry[BB*NC*SS];
__device__ float g_x0[BB*TT];

// packed fp32x2 FMA (PTX ISA 8.6, sm_100 family feature)
#define FMA2(acc, a, b) \
    asm("fma.rn.f32x2 %0, %1, %2, %0;" : "+l"(acc) : "l"(a), "l"(b))

__device__ __forceinline__ float acc_sum(unsigned long long a) {
    float lo, hi;
    asm("mov.b64 {%0,%1}, %2;" : "=f"(lo), "=f"(hi) : "l"(a));
    return lo + hi;
}

// ---------------------------------------------------------------------------
// Weight tile: 128 rows (s) x 128 cols (k) fp32, 512B/row.
// 16B chunk c of row s stored at chunk index c ^ ((s>>2)&7).
//   store: fixed s, c = lane -> XOR permutation -> conflict-free
//   gemm read: s = 4*tx+i, fixed c -> chunk = c ^ (tx&7): 8-lane phases hit
//              8 distinct chunks mod 8 -> distinct bank groups -> conflict-free
// Byte addr = (s<<9) ^ (chunk<<4) -> per-load addr = P ^ (c<<4), 1 LOP3/load.
// ---------------------------------------------------------------------------
__device__ __forceinline__ void load_w_sw(float* wp, const float* __restrict__ Wg, int tid) {
    const float4* wg4 = (const float4*)Wg;
#pragma unroll
    for (int k = 0; k < 16; k++) {
        int f = tid + k * NTHR;         // 4096 float4 chunks
        int s = f >> 5, c = f & 31;
        uint32_t addr = ((uint32_t)s << 9) ^ ((uint32_t)(c ^ ((s >> 2) & 7)) << 4);
        *(float4*)((char*)wp + addr) = wg4[f];
    }
}

// ---------------------------------------------------------------------------
// 64x128x128 GEMM tile, 256 threads, f32x2 K-pairing.
// tx = tid&31 -> cols 4tx..4tx+3 ; ty = tid>>5 (0..7) -> rows 8ty..8ty+7.
// ---------------------------------------------------------------------------
__device__ __forceinline__ void gemm256(const float* __restrict__ xs,
                                        const float* __restrict__ wp,
                                        int rowb, int col,
                                        unsigned long long acc[8][4]) {
#pragma unroll
    for (int j = 0; j < 8; j++)
#pragma unroll
        for (int i = 0; i < 4; i++) acc[j][i] = 0ULL;

    uint32_t P[4];
#pragma unroll
    for (int i = 0; i < 4; i++) {
        int s = col + i;
        P[i] = ((uint32_t)s << 9) ^ ((uint32_t)((s >> 2) & 7) << 4);
    }
    const char* wpb = (const char*)wp;

#pragma unroll 4
    for (int c = 0; c < 32; c++) {
        ulonglong2 wv[4];
#pragma unroll
        for (int i = 0; i < 4; i++)
            wv[i] = *(const ulonglong2*)(wpb + (P[i] ^ ((uint32_t)c << 4)));
#pragma unroll
        for (int j = 0; j < 8; j++) {
            ulonglong2 xv = *(const ulonglong2*)(xs + (rowb + j) * 128 + c * 4);
#pragma unroll
            for (int i = 0; i < 4; i++) {
                FMA2(acc[j][i], xv.x, wv[i].x);
                FMA2(acc[j][i], xv.y, wv[i].y);
            }
        }
    }
}

extern __shared__ float sm[];

// ---------------------------------------------------------------------------
// k1: C/dt/B GEMMs + pointwise + local chunk scan, 96KB smem -> 2 CTAs/SM
// smem: xs 32KB (x -> u) | wp 64KB (weights -> la)
// ---------------------------------------------------------------------------
#define XS_OFF 0
#define WP_OFF (ROWS*128)
#define K1_SMEM ((ROWS*128 + 128*128) * 4)   // 98304 B

__global__ void __launch_bounds__(NTHR, 2)
k1(const float* __restrict__ x, const float* __restrict__ log_A,
   const float* __restrict__ W_B, const float* __restrict__ W_C,
   const float* __restrict__ W_dt, const float* __restrict__ b_dt) {
    float* xs = sm + XS_OFF;    // x tile; becomes u after B GEMM
    float* wp = sm + WP_OFF;    // weight tile; la overlays it for the scan

    const int tid = threadIdx.x;
    const int row0 = blockIdx.x * ROWS;
    const int tx = tid & 31, ty = tid >> 5;
    const int col = 4 * tx, rowb = 8 * ty;

    // x tile (row-major, pitch 128) + x0 stash
    {
        const float4* xg = (const float4*)(x + (size_t)row0 * DD);
        float4* xs4 = (float4*)xs;
#pragma unroll
        for (int k = 0; k < 8; k++) xs4[tid + k * NTHR] = xg[tid + k * NTHR];
    }
    if (tid < ROWS) g_x0[row0 + tid] = x[(size_t)(row0 + tid) * DD];

    unsigned long long acc[8][4];

    // ---- C GEMM -> global ----
    load_w_sw(wp, W_C, tid);
    __syncthreads();
    gemm256(xs, wp, rowb, col, acc);
#pragma unroll
    for (int j = 0; j < 8; j++) {
        float4 v = make_float4(acc_sum(acc[j][0]), acc_sum(acc[j][1]),
                               acc_sum(acc[j][2]), acc_sum(acc[j][3]));
        *(float4*)(g_C + (size_t)(row0 + rowb + j) * SS + col) = v;
    }
    __syncthreads();

    // ---- dt GEMM -> dt in registers ----
    load_w_sw(wp, W_dt, tid);
    __syncthreads();
    gemm256(xs, wp, rowb, col, acc);
    float dt[8][4];
    {
        float bi[4];
#pragma unroll
        for (int i = 0; i < 4; i++) bi[i] = b_dt[col + i];
#pragma unroll
        for (int j = 0; j < 8; j++)
#pragma unroll
            for (int i = 0; i < 4; i++) {
                float z = acc_sum(acc[j][i]) + bi[i];
                float sp = fmaxf(z, 0.0f) + log1pf(__expf(-fabsf(z)));
                dt[j][i] = fminf(sp, 1.0f);
            }
    }
    __syncthreads();

    // ---- B GEMM ----
    load_w_sw(wp, W_B, tid);
    __syncthreads();
    gemm256(xs, wp, rowb, col, acc);
    __syncthreads();   // all xs/wp reads done; both regions now reusable

    // u = Bx*dt -> xs ; la = clip(dt*A) -> wp (overlay)
    {
        float Ai[4];
#pragma unroll
        for (int i = 0; i < 4; i++) Ai[i] = -fminf(expf(log_A[col + i]), 10.0f);
#pragma unroll
        for (int j = 0; j < 8; j++) {
            float4 uv = make_float4(acc_sum(acc[j][0]) * dt[j][0],
                                    acc_sum(acc[j][1]) * dt[j][1],
                                    acc_sum(acc[j][2]) * dt[j][2],
                                    acc_sum(acc[j][3]) * dt[j][3]);
            float4 lv = make_float4(fminf(fmaxf(dt[j][0] * Ai[0], -0.5f), 0.0f),
                                    fminf(fmaxf(dt[j][1] * Ai[1], -0.5f), 0.0f),
                                    fminf(fmaxf(dt[j][2] * Ai[2], -0.5f), 0.0f),
                                    fminf(fmaxf(dt[j][3] * Ai[3], -0.5f), 0.0f));
            *(float4*)(xs + (rowb + j) * 128 + col) = uv;
            *(float4*)(wp + (rowb + j) * 128 + col) = lv;
        }
    }
    __syncthreads();

    // ---- local chunk scan (1 chunk x 128 states), h0 = 0 ----
    if (tid < 128) {
        const int s = tid;
        size_t gb = (size_t)row0 * SS + s;
        float cum = 0.0f, Ssum = 0.0f;
#pragma unroll 4
        for (int t = 0; t < CK; t++) {
            cum += wp[t * 128 + s];
            float logp = fmaxf(cum, -30.0f);       // cum <= 0 already
            float pv = __expf(logp), pinv = __expf(-logp);
            Ssum = fmaf(xs[t * 128 + s], pinv, Ssum);
            g_hloc[gb + (size_t)t * 128] = pv * Ssum;
            g_p[gb + (size_t)t * 128] = pv;
        }
    }
}

// ---------------------------------------------------------------------------
// k2: cross-chunk carry scan
// ---------------------------------------------------------------------------
__global__ void k2_carry() {
    const int b = blockIdx.x, s = threadIdx.x;
    float h0 = 0.0f;
    for (int c0 = 0; c0 < NC; c0 += 16) {
        float hl[16], pp[16];
#pragma unroll
        for (int k = 0; k < 16; k++) {
            size_t idx = (size_t)(b * TT + (c0 + k) * CK + (CK - 1)) * SS + s;
            hl[k] = g_hloc[idx];
            pp[k] = g_p[idx];
        }
#pragma unroll
        for (int k = 0; k < 16; k++) {
            g_carry[(size_t)(b * NC + c0 + k) * SS + s] = h0;
            h0 = fmaf(pp[k], h0, hl[k]);
        }
    }
}

// ---------------------------------------------------------------------------
// k3: h = hloc + p*h0; y = sum(C*h); out = h@W_out^T + y*x0
// smem: hs 32KB | wp 64KB | ysh 64 | h0s 128 | x0s 64 -> ~97KB, 2 CTAs/SM
// ---------------------------------------------------------------------------
#define HS_OFF 0
#define WP3_OFF (ROWS*128)
#define YS_OFF (WP3_OFF + 128*128)
#define H0_OFF (YS_OFF + 64)
#define X0_OFF (H0_OFF + 128)
#define K3_SMEM ((X0_OFF + 64) * 4)

__global__ void __launch_bounds__(NTHR, 2)
k3(const float* __restrict__ W_out, float* __restrict__ out) {
    float* hs  = sm + HS_OFF;
    float* wp  = sm + WP3_OFF;
    float* ysh = sm + YS_OFF;
    float* h0s = sm + H0_OFF;
    float* x0s = sm + X0_OFF;

    const int tid = threadIdx.x;
    const int row0 = blockIdx.x * ROWS;
    const int b = row0 / TT;
    const int c0 = (row0 % TT) / CK;

    if (tid < 128) h0s[tid] = g_carry[(size_t)(b * NC + c0) * SS + tid];
    if (tid >= 128 && tid < 128 + ROWS) x0s[tid - 128] = g_x0[row0 + tid - 128];
    load_w_sw(wp, W_out, tid);
    __syncthreads();

    // h assembly + y reduction: 8 warps x 8 rows, lane covers 4 s
    {
        const int l = tid & 31, wgrp = tid >> 5;
        const int s4 = 4 * l;
#pragma unroll 2
        for (int rr = 0; rr < 8; rr++) {
            int r = wgrp * 8 + rr;
            size_t base = (size_t)(row0 + r) * SS + s4;
            float4 hl4 = *(const float4*)(g_hloc + base);
            float4 pp4 = *(const float4*)(g_p + base);
            float4 cc4 = *(const float4*)(g_C + base);
            float4 h04 = *(const float4*)(h0s + s4);
            float4 h;
            h.x = fmaf(pp4.x, h04.x, hl4.x);
            h.y = fmaf(pp4.y, h04.y, hl4.y);
            h.z = fmaf(pp4.z, h04.z, hl4.z);
            h.w = fmaf(pp4.w, h04.w, hl4.w);
            *(float4*)(hs + r * 128 + s4) = h;
            float yp = cc4.x * h.x + cc4.y * h.y + cc4.z * h.z + cc4.w * h.w;
#pragma unroll
            for (int d = 16; d; d >>= 1) yp += __shfl_xor_sync(0xffffffffu, yp, d);
            if (l == 0) ysh[r] = yp;
        }
    }
    __syncthreads();

    // out GEMM
    const int tx = tid & 31, ty = tid >> 5;
    const int col = 4 * tx, rowb = 8 * ty;
    unsigned long long acc[8][4];
    gemm256(hs, wp, rowb, col, acc);
#pragma unroll
    for (int j = 0; j < 8; j++) {
        float yx = ysh[rowb + j] * x0s[rowb + j];
        float4 v = make_float4(acc_sum(acc[j][0]) + yx, acc_sum(acc[j][1]) + yx,
                               acc_sum(acc[j][2]) + yx, acc_sum(acc[j][3]) + yx);
        *(float4*)(out + (size_t)(row0 + rowb + j) * DD + col) = v;
    }
}

// ---------------------------------------------------------------------------
// Launch
// ---------------------------------------------------------------------------
extern "C" void kernel_launch(void* const* d_in, const int* in_sizes, int n_in,
                              void* d_out, int out_size) {
    const float* x     = (const float*)d_in[0];
    const float* log_A = (const float*)d_in[1];
    const float* W_B   = (const float*)d_in[2];
    const float* W_C   = (const float*)d_in[3];
    const float* W_dt  = (const float*)d_in[4];
    const float* b_dt  = (const float*)d_in[5];
    const float* W_out = (const float*)d_in[6];
    float* out = (float*)d_out;

    cudaFuncSetAttribute(k1, cudaFuncAttributeMaxDynamicSharedMemorySize, K1_SMEM);
    cudaFuncSetAttribute(k3, cudaFuncAttributeMaxDynamicSharedMemorySize, K3_SMEM);

    k1<<<NB, NTHR, K1_SMEM>>>(x, log_A, W_B, W_C, W_dt, b_dt);
    k2_carry<<<BB, 128>>>();
    k3<<<NB, NTHR, K3_SMEM>>>(W_out, out);
}